// round 13
// baseline (speedup 1.0000x reference)
#include <cuda_runtime.h>
#include <math.h>

#define T_ENC   40
#define HID     128
#define DIN     512
#define STATE   256
#define ACT     18
#define BATCHN  1024
#define ROWS    7
#define KMAX_G  12
#define SLOW_CAP 64

// Transposed w_in: w_inT[d*128 + h] = w_in[h*512 + d]; row DIN is zeros (sentinel)
__device__ float    g_winT[(DIN + 1) * HID];
__device__ float    g_G[BATCHN * KMAX_G * HID];      // per-row period-group sums
__device__ unsigned g_slow[BATCHN * SLOW_CAP];       // (t_occ<<16)|d, sorted
__device__ int      g_ns[BATCHN];
__device__ unsigned g_kmask[BATCHN];

__global__ void transpose_win(const float* __restrict__ w_in) {
    int i = blockIdx.x * blockDim.x + threadIdx.x;   // 65536 elements
    int h = i >> 9, d = i & 511;
    g_winT[d * HID + h] = w_in[i];
    if (i < HID) g_winT[DIN * HID + i] = 0.f;        // zero sentinel row
}

// ============================================================================
// Kernel A: per-row prologue. One 128-thread CTA per batch row.
// Encoder periods -> class lists -> G build (direct LDG, d-ascending) -> global.
// ============================================================================
__global__ void __launch_bounds__(HID)
snn_prologue(const float* __restrict__ x)
{
    __shared__ float    G[KMAX_G * HID];
    __shared__ unsigned lists[544];
    __shared__ uint4    blt[4][4];
    __shared__ unsigned slow_s[SLOW_CAP];
    __shared__ int      ns_s;
    __shared__ unsigned kmask_s;

    const int b    = blockIdx.x;
    const int h    = threadIdx.x;
    const int myw  = h >> 5;
    const int lane = h & 31;
    const unsigned lanelt = (1u << lane) - 1u;

    if (h == 0) { ns_s = 0; kmask_s = 0u; }
    #pragma unroll
    for (int k = 0; k < KMAX_G; ++k) G[k * HID + h] = 0.f;
    __syncthreads();

    // ---- encoder: 4 sims, ballots stashed ----
    unsigned pb = 0u, mybits = 0u;
    #pragma unroll 1
    for (int q = 0; q < 4; ++q) {
        const int d = q * HID + h;
        float xv = x[b * STATE + (d & 255)];
        float c  = 50.f * xv;
        float I  = (d < 256) ? fmaxf(c, 0.f) : fmaxf(-c, 0.f);
        int p = 0;
        if (I > 1.0f) {                      // I<=1 provably never crosses threshold
            float v = 0.f;
            #pragma unroll 1
            for (int s = 1; s <= T_ENC; ++s) {
                v = v + 0.1f * (I - v);
                if (v - 1.0f > 0.0f) { p = s; break; }
            }
        }
        pb |= (unsigned)p << (8 * q);
        if (p >= 1 && p <= KMAX_G) mybits |= 1u << (p - 1);
        int cls = 0;
        if (p) cls = (p <= 3) ? p : (p <= KMAX_G ? 4 : 5);
        if (cls == 5) {                      // one slow entry per occurrence time
            for (int m = p; m <= T_ENC; m += p) {
                int slot = atomicAdd(&ns_s, 1);
                if (slot < SLOW_CAP) slow_s[slot] = ((unsigned)m << 16) | (unsigned)d;
            }
        }
        unsigned c1 = __ballot_sync(0xffffffffu, cls == 1);
        unsigned c2 = __ballot_sync(0xffffffffu, cls == 2);
        unsigned c3 = __ballot_sync(0xffffffffu, cls == 3);
        unsigned c4 = __ballot_sync(0xffffffffu, cls == 4);
        if (lane == 0) blt[q][myw] = make_uint4(c1, c2, c3, c4);
    }
    {
        unsigned wm = __reduce_or_sync(0xffffffffu, mybits);
        if (lane == 0 && wm) atomicOr(&kmask_s, wm);
    }
    __syncthreads();

    // ---- pass 1: global class totals -> segment starts ----
    int t1 = 0, t2 = 0, t3 = 0, t4 = 0;
    #pragma unroll
    for (int q = 0; q < 4; ++q)
        #pragma unroll
        for (int w = 0; w < 4; ++w) {
            uint4 v = blt[q][w];
            t1 += __popc(v.x); t2 += __popc(v.y); t3 += __popc(v.z); t4 += __popc(v.w);
        }
    const int P1 = (t1 + 3) & ~3, P2 = (t2 + 3) & ~3, P3 = (t3 + 3) & ~3, P4 = (t4 + 3) & ~3;
    const int S1 = 0, S2 = P1, S3 = P1 + P2, S4 = P1 + P2 + P3;
    const int E4 = S4 + P4;

    // ---- pass 2: write list entries (d-ascending within each class) ----
    {
        int q1 = 0, q2 = 0, q3 = 0, q4 = 0;
        #pragma unroll
        for (int q = 0; q < 4; ++q) {
            uint4 v0 = blt[q][0], v1 = blt[q][1], v2 = blt[q][2], v3 = blt[q][3];
            int p = (int)((pb >> (8 * q)) & 255u);
            int cls = 0;
            if (p) cls = (p <= 3) ? p : (p <= KMAX_G ? 4 : 5);
            if (cls >= 1 && cls <= 4) {
                unsigned s0, s1, s2, s3;
                if (cls == 1)      { s0 = v0.x; s1 = v1.x; s2 = v2.x; s3 = v3.x; }
                else if (cls == 2) { s0 = v0.y; s1 = v1.y; s2 = v2.y; s3 = v3.y; }
                else if (cls == 3) { s0 = v0.z; s1 = v1.z; s2 = v2.z; s3 = v3.z; }
                else               { s0 = v0.w; s1 = v1.w; s2 = v2.w; s3 = v3.w; }
                unsigned smy = (myw == 0) ? s0 : (myw == 1) ? s1 : (myw == 2) ? s2 : s3;
                int wo = 0;
                if (myw > 0) wo += __popc(s0);
                if (myw > 1) wo += __popc(s1);
                if (myw > 2) wo += __popc(s2);
                int rank = __popc(smy & lanelt);
                int Sc   = (cls == 1) ? S1 : (cls == 2) ? S2 : (cls == 3) ? S3 : S4;
                int qpre = (cls == 1) ? q1 : (cls == 2) ? q2 : (cls == 3) ? q3 : q4;
                unsigned entry = (unsigned)(q * HID + h);
                if (cls == 4) entry |= (unsigned)p << 10;
                lists[Sc + qpre + wo + rank] = entry;
            }
            q1 += __popc(v0.x) + __popc(v1.x) + __popc(v2.x) + __popc(v3.x);
            q2 += __popc(v0.y) + __popc(v1.y) + __popc(v2.y) + __popc(v3.y);
            q3 += __popc(v0.z) + __popc(v1.z) + __popc(v2.z) + __popc(v3.z);
            q4 += __popc(v0.w) + __popc(v1.w) + __popc(v2.w) + __popc(v3.w);
        }
    }
    if (h < 4) {                             // pad each class segment to mult of 4
        int c  = h + 1;
        int nn = (c == 1) ? t1 : (c == 2) ? t2 : (c == 3) ? t3 : t4;
        int pn = (nn + 3) & ~3;
        int st = (c == 1) ? S1 : (c == 2) ? S2 : (c == 3) ? S3 : S4;
        unsigned sent = (c < 4) ? (unsigned)DIN : ((unsigned)DIN | (4u << 10));
        for (int j = nn; j < pn; ++j) lists[st + j] = sent;
    }
    __syncthreads();

    // ---- G build: direct LDG from g_winT, list-driven (bit-identical order) ----
    {
        float r1 = 0.f, r2 = 0.f, r3 = 0.f;
        const unsigned* L = lists;
        int i = 0;
        #pragma unroll 1
        for (; i < S2; i += 4) {
            uint4 ee = *(const uint4*)&L[i];
            r1 += __ldg(&g_winT[ee.x * HID + h]); r1 += __ldg(&g_winT[ee.y * HID + h]);
            r1 += __ldg(&g_winT[ee.z * HID + h]); r1 += __ldg(&g_winT[ee.w * HID + h]);
        }
        #pragma unroll 1
        for (; i < S3; i += 4) {
            uint4 ee = *(const uint4*)&L[i];
            r2 += __ldg(&g_winT[ee.x * HID + h]); r2 += __ldg(&g_winT[ee.y * HID + h]);
            r2 += __ldg(&g_winT[ee.z * HID + h]); r2 += __ldg(&g_winT[ee.w * HID + h]);
        }
        #pragma unroll 1
        for (; i < S4; i += 4) {
            uint4 ee = *(const uint4*)&L[i];
            r3 += __ldg(&g_winT[ee.x * HID + h]); r3 += __ldg(&g_winT[ee.y * HID + h]);
            r3 += __ldg(&g_winT[ee.z * HID + h]); r3 += __ldg(&g_winT[ee.w * HID + h]);
        }
        #pragma unroll 1
        for (; i < E4; i += 4) {
            uint4 ee = *(const uint4*)&L[i];
            G[((ee.x >> 10) - 1) * HID + h] += __ldg(&g_winT[(ee.x & 1023u) * HID + h]);
            G[((ee.y >> 10) - 1) * HID + h] += __ldg(&g_winT[(ee.y & 1023u) * HID + h]);
            G[((ee.z >> 10) - 1) * HID + h] += __ldg(&g_winT[(ee.z & 1023u) * HID + h]);
            G[((ee.w >> 10) - 1) * HID + h] += __ldg(&g_winT[(ee.w & 1023u) * HID + h]);
        }
        G[0 * HID + h] = r1;
        G[1 * HID + h] = r2;
        G[2 * HID + h] = r3;
    }

    if (h == 0) {                            // sort slow list ascending (t_occ, d)
        int n = ns_s; if (n > SLOW_CAP) n = SLOW_CAP;
        for (int i = 1; i < n; ++i) {
            unsigned key = slow_s[i];
            int j = i - 1;
            while (j >= 0 && slow_s[j] > key) { slow_s[j + 1] = slow_s[j]; --j; }
            slow_s[j + 1] = key;
        }
        ns_s = n;
    }
    __syncthreads();

    // ---- write out ----
    #pragma unroll
    for (int k = 0; k < KMAX_G; ++k)
        g_G[(b * KMAX_G + k) * HID + h] = G[k * HID + h];
    if (h < SLOW_CAP) g_slow[b * SLOW_CAP + h] = slow_s[h];
    if (h == 0) { g_ns[b] = ns_s; g_kmask[b] = kmask_s; }
}

// ============================================================================
// Kernel B: main recurrence + readout. 7 rows per 896-thread CTA.
// ============================================================================
struct __align__(16) RowSmem {
    float    G[KMAX_G * HID];   // 6144  B
    int      lsth[2][2][68];    // 1088  B : double-buffered half-split spike lists
    unsigned hist[T_ENC][4];    // 640   B
    float    u[T_ENC * 19];     // 3040  B
    unsigned slow[SLOW_CAP];    // 256   B
    float    ms[20];            // 80    B
    int      cseg[2];           // 8     B : per-sub-list entry counts (mult of 2)
    int      pad_[2];           // 8
};

struct Shm {
    float    wrT[129 * HID];    // 66048 B : w_rec^T (row 128 = zeros)
    float    wa[19 * 129 + 1];  // 9808  B
    unsigned divm[T_ENC];       // 160   B
    RowSmem  row[ROWS];
};  // ~154 KB

#define RBAR(r) asm volatile("bar.sync %0, %1;" :: "r"((r) + 1), "r"(128) : "memory")

__global__ void __launch_bounds__(ROWS * HID, 1)
snn_main(const float* __restrict__ w_rec,
         const float* __restrict__ w_actor,
         const float* __restrict__ w_critic,
         float* __restrict__ out)
{
    extern __shared__ unsigned char sraw[];
    Shm* S = (Shm*)sraw;

    const int tid  = threadIdx.x;
    const int row  = tid >> 7;
    const int h    = tid & 127;
    const int myw  = h >> 5;
    const int lane = h & 31;
    const unsigned lanelt = (1u << lane) - 1u;
    int b = blockIdx.x * ROWS + row;
    const bool active = (b < BATCHN);
    if (!active) b = BATCHN - 1;             // clamp; garbage compute, no output

    // ---- staging: pure coalesced copies ----
    for (int i = tid; i < 129 * HID; i += ROWS * HID) {
        int j = i >> 7, hh = i & 127;
        S->wrT[i] = (j < 128) ? w_rec[hh * HID + j] : 0.f;
    }
    for (int i = tid; i < 19 * 129; i += ROWS * HID) {
        int a = i / 129, j = i - a * 129;
        float v = 0.f;
        if (j < 128) v = (a < ACT) ? w_actor[a * HID + j] : w_critic[j];
        S->wa[i] = v;
    }
    if (tid < T_ENC) {
        unsigned m = 0u;
        int n = tid + 1;
        #pragma unroll
        for (int k = 1; k <= KMAX_G; ++k)
            if (n % k == 0) m |= 1u << (k - 1);
        S->divm[tid] = m;
    }

    RowSmem& R = S->row[row];
    #pragma unroll
    for (int k = 0; k < KMAX_G; ++k)
        R.G[k * HID + h] = g_G[(b * KMAX_G + k) * HID + h];
    if (h < SLOW_CAP) R.slow[h] = g_slow[b * SLOW_CAP + h];
    if (h == 0) { R.cseg[0] = 0; R.cseg[1] = 0; }
    const int ns = g_ns[b];
    const unsigned kmask = g_kmask[b];
    __syncthreads();
    if (!active) return;                     // only named barriers remain

    // ==== main 40-step recurrence: half-warp paired gather (R10 ordering) ====
    float v = 0.f, ci = 0.f;
    int cur = 0;                             // lsth[cur] holds z_{t-1} (empty at t=0)
    int sc = 0;                              // slow-list cursor (sorted by t_occ)

    const int half = lane >> 4;
    const int pr   = lane & 15;
    const unsigned wrT_pair = (unsigned)__cvta_generic_to_shared(S->wrT)
                            + (unsigned)((myw * 32 + 2 * pr) * 4);

    #pragma unroll 1
    for (int t = 0; t < T_ENC; ++t) {
        float vdec = v + 0.1f * (ci - v);
        float idec = ci - 0.2f * ci;
        bool  sp   = (vdec - 1.0f) > 0.0f;
        v = sp ? 0.f : vdec;

        unsigned bal = __ballot_sync(0xffffffffu, sp);
        if (lane == 0) R.hist[t][myw] = bal;
        RBAR(row);                           // hist[t] + lsth[cur] (z_{t-1}) visible

        if (t == T_ENC - 1) break;           // z_39 recurrent effects never consumed

        // paired gather over my half of z_{t-1}: packed f32x2, LDS.64 per entry
        unsigned long long A = 0ull, B = 0ull;
        {
            int m = R.cseg[cur];             // entries per sub-list (mult of 2)
            const int* L = R.lsth[cur][half];
            #pragma unroll 1
            for (int i = 0; i < m; i += 2) {
                int2 jj = *(const int2*)&L[i];
                unsigned long long w0, w1;
                asm volatile("ld.shared.b64 %0,[%1];" : "=l"(w0) : "r"(wrT_pair + (unsigned)jj.x * 512u));
                asm volatile("ld.shared.b64 %0,[%1];" : "=l"(w1) : "r"(wrT_pair + (unsigned)jj.y * 512u));
                asm volatile("add.rn.f32x2 %0,%0,%1;" : "+l"(A) : "l"(w0));
                asm volatile("add.rn.f32x2 %0,%0,%1;" : "+l"(B) : "l"(w1));
            }
        }

        // compact z_t into half-split lists lsth[cur^1] (skip at t=38)
        if (t < T_ENC - 2) {
            unsigned m0 = R.hist[t][0], m1 = R.hist[t][1], m2 = R.hist[t][2], m3 = R.hist[t][3];
            int cnt = __popc(m0) + __popc(m1) + __popc(m2) + __popc(m3);
            if (sp) {
                int r_  = __popc(bal & lanelt);
                int off = 0;
                if (myw > 0) off += __popc(m0);
                if (myw > 1) off += __popc(m1);
                if (myw > 2) off += __popc(m2);
                int rk = off + r_;
                R.lsth[cur ^ 1][rk & 1][rk >> 1] = h;
            }
            int cnt4 = (cnt + 3) & ~3;
            if (h >= cnt && h < cnt4) R.lsth[cur ^ 1][h & 1][h >> 1] = 128;  // sentinel
            if (h == 0) R.cseg[cur ^ 1] = cnt4 >> 1;
        }

        // combine halves + redistribute pair sums (no barrier)
        float rec;
        {
            unsigned long long Sab;
            asm("add.rn.f32x2 %0,%1,%2;" : "=l"(Sab) : "l"(A), "l"(B));
            unsigned slo_u, shi_u;
            asm("mov.b64 {%0,%1},%2;" : "=r"(slo_u), "=r"(shi_u) : "l"(Sab));
            float slo = __uint_as_float(slo_u);
            float shi = __uint_as_float(shi_u);
            slo += __shfl_xor_sync(0xffffffffu, slo, 16);
            shi += __shfl_xor_sync(0xffffffffu, shi, 16);
            float rl = __shfl_sync(0xffffffffu, slo, lane >> 1);
            float rh = __shfl_sync(0xffffffffu, shi, lane >> 1);
            rec = (lane & 1) ? rh : rl;
        }

        // encoded input current
        float inp = 0.f;
        {
            unsigned dm = S->divm[t] & kmask;
            while (dm) { int kk = __ffs(dm) - 1; dm &= dm - 1; inp += R.G[kk * HID + h]; }
            while (sc < ns && (int)(R.slow[sc] >> 16) == t + 1) {
                inp += g_winT[(R.slow[sc] & 0xffffu) * HID + h];
                ++sc;
            }
        }

        ci = idec + inp + rec;
        cur ^= 1;
    }

    // ==== epilogue phase 1: u[t][a] = z_t . w_ro[a]; t-major ====
    #pragma unroll 1
    for (int pp = h; pp < T_ENC * 19; pp += HID) {
        int t = pp / 19;
        int a = pp - t * 19;
        const float* wrow = &S->wa[a * 129];
        float s = 0.f;
        #pragma unroll
        for (int w = 0; w < 4; ++w) {
            unsigned m = R.hist[t][w];
            int base = w * 32;
            while (m) { int l = __ffs(m) - 1; m &= m - 1; s += wrow[base + l]; }
        }
        R.u[t * 19 + a] = s;
    }
    RBAR(row);

    // ==== epilogue phase 2: LI recurrence + max, lanes 0..18 ====
    if (h < ACT + 1) {
        float ia = 0.f, va = 0.f, mmax = -INFINITY;
        #pragma unroll 1
        for (int t = 0; t < T_ENC; ++t) {
            float nva = va + 0.1f * (ia - va);
            ia = (ia - 0.2f * ia) + R.u[t * 19 + h];
            va = nva;
            mmax = fmaxf(mmax, nva);
        }
        R.ms[h] = mmax;
    }
    RBAR(row);

    if (h == 0) {
        float mx = -INFINITY;
        #pragma unroll
        for (int a = 0; a < ACT; ++a) mx = fmaxf(mx, R.ms[a]);
        float e[ACT], s = 0.f;
        #pragma unroll
        for (int a = 0; a < ACT; ++a) { e[a] = expf(R.ms[a] - mx); s += e[a]; }
        float inv = 1.f / s;
        #pragma unroll
        for (int a = 0; a < ACT; ++a) out[b * ACT + a] = e[a] * inv;
        out[BATCHN * ACT + b] = R.ms[ACT];
    }
}

extern "C" void kernel_launch(void* const* d_in, const int* in_sizes, int n_in,
                              void* d_out, int out_size)
{
    const float* x        = (const float*)d_in[0];
    const float* w_in     = (const float*)d_in[1];
    const float* w_rec    = (const float*)d_in[2];
    const float* w_actor  = (const float*)d_in[3];
    const float* w_critic = (const float*)d_in[4];
    float* out = (float*)d_out;

    transpose_win<<<256, 256>>>(w_in);
    snn_prologue<<<BATCHN, HID>>>(x);

    cudaFuncSetAttribute(snn_main, cudaFuncAttributeMaxDynamicSharedMemorySize, (int)sizeof(Shm));
    int grid = (BATCHN + ROWS - 1) / ROWS;
    snn_main<<<grid, ROWS * HID, sizeof(Shm)>>>(w_rec, w_actor, w_critic, out);
}

// round 14
// speedup vs baseline: 1.3000x; 1.3000x over previous
#include <cuda_runtime.h>
#include <math.h>

#define T_ENC   40
#define HID     128
#define DIN     512
#define STATE   256
#define ACT     18
#define BATCHN  1024
#define ROWS    7
#define KMAX_G  20
#define SLOW_CAP 64

// Transposed w_in: w_inT[d*128 + h] = w_in[h*512 + d]
__device__ float g_winT[DIN * HID];

struct __align__(16) RowSmem {
    float    G[KMAX_G * HID];   // 10240 B : period-group sums k=1..20
    int      lsth[2][2][68];    // 1088  B : double-buffered half-split spike lists
    unsigned lists[4 * 144];    // 2304  B : per-chunk class-grouped feature lists (padded x4)
    uint4    wcnt[4];           // 64    B : per-warp class counts (scratch)
    int      cnts[4][4];        // 64    B : padded class counts per chunk
    unsigned hist[T_ENC][4];    // 640   B : per-step ballot words
    float    u[T_ENC * 19];     // 3040  B : readout drive u[t*19+a]
    unsigned slow[SLOW_CAP];    // 256   B : d | (k<<16), sorted by (k,d)
    float    ms[20];            // 80    B
    int      cseg[2];           // 8     B : per-sub-list entry counts (mult of 4)
    int      ns;                // 4
    unsigned kmask_s;           // 4     B : bit k-1 set iff G column k nonzero
};

struct Shm {
    float    wrT[129 * HID];    // 66048 B : w_rec^T (row 128 = zeros); chunk buffer in prologue
    float    wa[19 * 129 + 1];  // 9808  B : actor rows 0..17 + critic row 18, col 128 = 0
    unsigned divm[T_ENC];       // 160   B
    RowSmem  row[ROWS];
};  // ~201 KB

#define RBAR(r) asm volatile("bar.sync %0, %1;" :: "r"((r) + 1), "r"(128) : "memory")

// Tiled coalesced transpose: w_in [128,512] -> g_winT [512,128].
// Grid (16,4) of 32x32 tiles, block (32,8), smem-padded.
__global__ void transpose_win(const float* __restrict__ w_in) {
    __shared__ float tile[32][33];
    const int tx = threadIdx.x;          // 0..31
    const int ty = threadIdx.y;          // 0..7
    const int d0 = blockIdx.x * 32;      // d tile origin (0..480)
    const int h0 = blockIdx.y * 32;      // h tile origin (0..96)
    #pragma unroll
    for (int r = 0; r < 4; ++r) {
        int hh = ty + r * 8;
        tile[hh][tx] = w_in[(h0 + hh) * DIN + d0 + tx];   // coalesced read
    }
    __syncthreads();
    #pragma unroll
    for (int r = 0; r < 4; ++r) {
        int dd = ty + r * 8;
        g_winT[(d0 + dd) * HID + h0 + tx] = tile[tx][dd]; // coalesced write
    }
}

__global__ void __launch_bounds__(ROWS * HID, 1)
snn_kernel(const float* __restrict__ x,
           const float* __restrict__ w_in,
           const float* __restrict__ w_rec,
           const float* __restrict__ w_actor,
           const float* __restrict__ w_critic,
           float* __restrict__ out)
{
    extern __shared__ unsigned char sraw[];
    Shm* S = (Shm*)sraw;

    const int tid  = threadIdx.x;
    const int row  = tid >> 7;
    const int h    = tid & 127;
    const int myw  = h >> 5;
    const int lane = h & 31;
    const unsigned lanelt = (1u << lane) - 1u;
    int b = blockIdx.x * ROWS + row;
    const bool active = (b < BATCHN);
    if (!active) b = BATCHN - 1;             // clamp; garbage compute, no output

    // ---- stage w_actor/w_critic (padded) + divisor masks + zero sentinel row ----
    for (int i = tid; i < 19 * 129; i += ROWS * HID) {
        int a = i / 129, j = i - a * 129;
        float v = 0.f;
        if (j < 128) v = (a < ACT) ? w_actor[a * HID + j] : w_critic[j];
        S->wa[i] = v;
    }
    if (tid < T_ENC) {
        unsigned m = 0u;
        int n = tid + 1;
        #pragma unroll
        for (int k = 1; k <= KMAX_G; ++k)
            if (n % k == 0) m |= 1u << (k - 1);
        S->divm[tid] = m;
    }
    if (tid < HID) S->wrT[128 * HID + tid] = 0.f;   // sentinel row (j=128 -> zeros)

    RowSmem& R = S->row[row];
    if (h == 0) { R.ns = 0; R.cseg[0] = 0; R.cseg[1] = 0; R.kmask_s = 0u; }
    #pragma unroll
    for (int k = 0; k < KMAX_G; ++k) R.G[k * HID + h] = 0.f;
    RBAR(row);

    // ---- encoder + per-chunk class list build (4 rounds) ----
    for (int q = 0; q < 4; ++q) {
        const int d = q * HID + h;
        float xv = x[b * STATE + (d & 255)];
        float c  = 50.f * xv;
        float I  = (d < 256) ? fmaxf(c, 0.f) : fmaxf(-c, 0.f);
        int p = 0;
        if (I > 1.0f) {                      // I<=1 provably never crosses threshold
            float v = 0.f;
            #pragma unroll 1
            for (int s = 1; s <= T_ENC; ++s) {
                v = v + 0.1f * (I - v);
                if (v - 1.0f > 0.0f) { p = s; break; }
            }
        }
        int cls = 0;
        if (p) cls = (p <= 3) ? p : (p <= KMAX_G ? 4 : 5);
        if (cls == 5) {
            int slot = atomicAdd(&R.ns, 1);
            if (slot < SLOW_CAP) R.slow[slot] = (unsigned)d | ((unsigned)p << 16);
        }
        {   // nonzero-G column mask
            unsigned bit = (p >= 1 && p <= KMAX_G) ? (1u << (p - 1)) : 0u;
            unsigned wm = __reduce_or_sync(0xffffffffu, bit);
            if (lane == 0 && wm) atomicOr(&R.kmask_s, wm);
        }
        unsigned b1 = __ballot_sync(0xffffffffu, cls == 1);
        unsigned b2 = __ballot_sync(0xffffffffu, cls == 2);
        unsigned b3 = __ballot_sync(0xffffffffu, cls == 3);
        unsigned b4 = __ballot_sync(0xffffffffu, cls == 4);
        if (lane == 0)
            R.wcnt[myw] = make_uint4(__popc(b1), __popc(b2), __popc(b3), __popc(b4));
        RBAR(row);

        uint4 c0 = R.wcnt[0], c1 = R.wcnt[1], c2 = R.wcnt[2], c3 = R.wcnt[3];
        int n1 = c0.x + c1.x + c2.x + c3.x;
        int n2 = c0.y + c1.y + c2.y + c3.y;
        int n3 = c0.z + c1.z + c2.z + c3.z;
        int n4 = c0.w + c1.w + c2.w + c3.w;
        int p1 = (n1 + 3) & ~3, p2 = (n2 + 3) & ~3, p3 = (n3 + 3) & ~3, p4 = (n4 + 3) & ~3;

        if (cls >= 1 && cls <= 4) {
            unsigned bsel = (cls == 1) ? b1 : (cls == 2) ? b2 : (cls == 3) ? b3 : b4;
            int rank = __popc(bsel & lanelt);
            int st, wp;
            if (cls == 1) { st = 0;            wp = (myw>0?(int)c0.x:0)+(myw>1?(int)c1.x:0)+(myw>2?(int)c2.x:0); }
            else if (cls == 2) { st = p1;      wp = (myw>0?(int)c0.y:0)+(myw>1?(int)c1.y:0)+(myw>2?(int)c2.y:0); }
            else if (cls == 3) { st = p1+p2;   wp = (myw>0?(int)c0.z:0)+(myw>1?(int)c1.z:0)+(myw>2?(int)c2.z:0); }
            else { st = p1+p2+p3;              wp = (myw>0?(int)c0.w:0)+(myw>1?(int)c1.w:0)+(myw>2?(int)c2.w:0); }
            unsigned entry = (cls < 4) ? (unsigned)h : ((unsigned)h | ((unsigned)p << 8));
            R.lists[q * 144 + st + wp + rank] = entry;
        }
        if (h < 4) {                         // pad each class segment to mult of 4
            int nn = (h == 0) ? n1 : (h == 1) ? n2 : (h == 2) ? n3 : n4;
            int pn = (nn + 3) & ~3;
            int st = (h == 0) ? 0 : (h == 1) ? p1 : (h == 2) ? p1 + p2 : p1 + p2 + p3;
            unsigned sent = (h < 3) ? 128u : (128u | (4u << 8));   // row 128 = zeros
            for (int j = nn; j < pn; ++j) R.lists[q * 144 + st + j] = sent;
            R.cnts[q][h] = pn;
        }
        RBAR(row);                           // wcnt reused next round
    }

    if (h == 0) {                            // sort slow list by (k, d) for cursor walk
        int n = R.ns; if (n > SLOW_CAP) n = SLOW_CAP;
        for (int i = 1; i < n; ++i) {
            unsigned key = R.slow[i];
            int j = i - 1;
            while (j >= 0 && R.slow[j] > key) { R.slow[j + 1] = R.slow[j]; --j; }
            R.slow[j + 1] = key;
        }
        R.ns = n;
    }
    __syncthreads();
    const int ns = R.ns;
    const unsigned kmask = R.kmask_s;

    // ---- G build: stream w_inT through smem in 4 chunks, list-driven accumulation ----
    {
        float r1 = 0.f, r2 = 0.f, r3 = 0.f;
        for (int c = 0; c < 4; ++c) {
            const float4* src = (const float4*)(g_winT + c * 128 * HID);
            float4* dst = (float4*)S->wrT;
            #pragma unroll 2
            for (int i = tid; i < (128 * HID) / 4; i += ROWS * HID) dst[i] = src[i];
            __syncthreads();

            const unsigned* Lq = &R.lists[c * 144];
            const float* buf = S->wrT;
            int p1c = R.cnts[c][0], p2c = R.cnts[c][1], p3c = R.cnts[c][2], p4c = R.cnts[c][3];
            int e1 = p1c, e2 = e1 + p2c, e3 = e2 + p3c, e4 = e3 + p4c;
            int i = 0;
            #pragma unroll 1
            for (; i < e1; i += 4) {
                uint4 ee = *(const uint4*)&Lq[i];
                r1 += buf[ee.x * HID + h]; r1 += buf[ee.y * HID + h];
                r1 += buf[ee.z * HID + h]; r1 += buf[ee.w * HID + h];
            }
            #pragma unroll 1
            for (; i < e2; i += 4) {
                uint4 ee = *(const uint4*)&Lq[i];
                r2 += buf[ee.x * HID + h]; r2 += buf[ee.y * HID + h];
                r2 += buf[ee.z * HID + h]; r2 += buf[ee.w * HID + h];
            }
            #pragma unroll 1
            for (; i < e3; i += 4) {
                uint4 ee = *(const uint4*)&Lq[i];
                r3 += buf[ee.x * HID + h]; r3 += buf[ee.y * HID + h];
                r3 += buf[ee.z * HID + h]; r3 += buf[ee.w * HID + h];
            }
            #pragma unroll 1
            for (; i < e4; i += 4) {
                uint4 ee = *(const uint4*)&Lq[i];
                R.G[((ee.x >> 8) - 1) * HID + h] += buf[(ee.x & 255u) * HID + h];
                R.G[((ee.y >> 8) - 1) * HID + h] += buf[(ee.y & 255u) * HID + h];
                R.G[((ee.z >> 8) - 1) * HID + h] += buf[(ee.z & 255u) * HID + h];
                R.G[((ee.w >> 8) - 1) * HID + h] += buf[(ee.w & 255u) * HID + h];
            }
            __syncthreads();
        }
        R.G[0 * HID + h] = r1;
        R.G[1 * HID + h] = r2;
        R.G[2 * HID + h] = r3;
    }

    // ---- stage w_rec transposed (overwrites chunk buffer; row 128 = zeros) ----
    for (int i = tid; i < 129 * HID; i += ROWS * HID) {
        int j = i >> 7, hh = i & 127;
        S->wrT[i] = (j < 128) ? w_rec[hh * HID + j] : 0.f;
    }
    __syncthreads();
    if (!active) return;                     // only named barriers remain

    // ==== main 40-step recurrence: half-warp paired gather ====
    float v = 0.f, ci = 0.f;
    int cur = 0;                             // lsth[cur] holds z_{t-1} (empty at t=0)
    int sc = 0;                              // slow-list cursor (sorted by k)

    const int half = lane >> 4;              // which half of the spike list I process
    const int pr   = lane & 15;              // my h-pair within the warp
    const unsigned wrT_pair = (unsigned)__cvta_generic_to_shared(S->wrT)
                            + (unsigned)((myw * 32 + 2 * pr) * 4);

    #pragma unroll 1
    for (int t = 0; t < T_ENC; ++t) {
        // dynamics + ballot (z_t)
        float vdec = v + 0.1f * (ci - v);
        float idec = ci - 0.2f * ci;
        bool  sp   = (vdec - 1.0f) > 0.0f;
        v = sp ? 0.f : vdec;

        unsigned bal = __ballot_sync(0xffffffffu, sp);
        if (lane == 0) R.hist[t][myw] = bal;
        RBAR(row);                           // hist[t] + lsth[cur] (z_{t-1}) visible

        if (t == T_ENC - 1) break;           // z_39 recurrent effects never consumed

        // paired gather over my half of z_{t-1}: packed f32x2, LDS.64 per entry
        unsigned long long A = 0ull, B = 0ull;
        {
            int m = R.cseg[cur];             // entries per sub-list (mult of 4)
            const int* L = R.lsth[cur][half];
            #pragma unroll 1
            for (int i = 0; i < m; i += 4) {
                int4 jj = *(const int4*)&L[i];
                unsigned long long w0, w1, w2, w3;
                asm volatile("ld.shared.b64 %0,[%1];" : "=l"(w0) : "r"(wrT_pair + (unsigned)jj.x * 512u));
                asm volatile("ld.shared.b64 %0,[%1];" : "=l"(w1) : "r"(wrT_pair + (unsigned)jj.y * 512u));
                asm volatile("ld.shared.b64 %0,[%1];" : "=l"(w2) : "r"(wrT_pair + (unsigned)jj.z * 512u));
                asm volatile("ld.shared.b64 %0,[%1];" : "=l"(w3) : "r"(wrT_pair + (unsigned)jj.w * 512u));
                asm volatile("add.rn.f32x2 %0,%0,%1;" : "+l"(A) : "l"(w0));
                asm volatile("add.rn.f32x2 %0,%0,%1;" : "+l"(B) : "l"(w1));
                asm volatile("add.rn.f32x2 %0,%0,%1;" : "+l"(A) : "l"(w2));
                asm volatile("add.rn.f32x2 %0,%0,%1;" : "+l"(B) : "l"(w3));
            }
        }

        // compact z_t into half-split lists lsth[cur^1] (skip at t=38: never consumed)
        if (t < T_ENC - 2) {
            unsigned m0 = R.hist[t][0], m1 = R.hist[t][1], m2 = R.hist[t][2], m3 = R.hist[t][3];
            int cnt = __popc(m0) + __popc(m1) + __popc(m2) + __popc(m3);
            if (sp) {
                int r_  = __popc(bal & lanelt);
                int off = 0;
                if (myw > 0) off += __popc(m0);
                if (myw > 1) off += __popc(m1);
                if (myw > 2) off += __popc(m2);
                int rk = off + r_;
                R.lsth[cur ^ 1][rk & 1][rk >> 1] = h;
            }
            int cnt8 = (cnt + 7) & ~7;
            if (h >= cnt && h < cnt8) R.lsth[cur ^ 1][h & 1][h >> 1] = 128;  // sentinel
            if (h == 0) R.cseg[cur ^ 1] = cnt8 >> 1;
        }

        // combine halves + redistribute pair sums to per-h threads (no barrier)
        float rec;
        {
            unsigned long long Sab;
            asm("add.rn.f32x2 %0,%1,%2;" : "=l"(Sab) : "l"(A), "l"(B));
            unsigned slo_u, shi_u;
            asm("mov.b64 {%0,%1},%2;" : "=r"(slo_u), "=r"(shi_u) : "l"(Sab));
            float slo = __uint_as_float(slo_u);
            float shi = __uint_as_float(shi_u);
            slo += __shfl_xor_sync(0xffffffffu, slo, 16);
            shi += __shfl_xor_sync(0xffffffffu, shi, 16);
            float rl = __shfl_sync(0xffffffffu, slo, lane >> 1);
            float rh = __shfl_sync(0xffffffffu, shi, lane >> 1);
            rec = (lane & 1) ? rh : rl;
        }

        // encoded input current (kmask skips exactly-zero G columns: bit-safe)
        float inp = 0.f;
        {
            unsigned dm = S->divm[t] & kmask;
            while (dm) { int kk = __ffs(dm) - 1; dm &= dm - 1; inp += R.G[kk * HID + h]; }
            while (sc < ns && (int)(R.slow[sc] >> 16) == t + 1) {
                inp += g_winT[(R.slow[sc] & 0xffffu) * HID + h];
                ++sc;
            }
        }

        ci = idec + inp + rec;
        cur ^= 1;
    }

    // ==== epilogue phase 1: u[t][a] = z_t . w_ro[a]; t-major so lanes share masks ====
    #pragma unroll 1
    for (int pp = h; pp < T_ENC * 19; pp += HID) {
        int t = pp / 19;
        int a = pp - t * 19;
        const float* wrow = &S->wa[a * 129];
        float s = 0.f;
        #pragma unroll
        for (int w = 0; w < 4; ++w) {
            unsigned m = R.hist[t][w];
            int base = w * 32;
            while (m) { int l = __ffs(m) - 1; m &= m - 1; s += wrow[base + l]; }
        }
        R.u[t * 19 + a] = s;
    }
    RBAR(row);

    // ==== epilogue phase 2: LI recurrence + max, lanes 0..18 ====
    if (h < ACT + 1) {
        float ia = 0.f, va = 0.f, mmax = -INFINITY;
        #pragma unroll 1
        for (int t = 0; t < T_ENC; ++t) {
            float nva = va + 0.1f * (ia - va);       // uses pre-update ia
            ia = (ia - 0.2f * ia) + R.u[t * 19 + h];
            va = nva;
            mmax = fmaxf(mmax, nva);
        }
        R.ms[h] = mmax;
    }
    RBAR(row);

    if (h == 0) {
        float mx = -INFINITY;
        #pragma unroll
        for (int a = 0; a < ACT; ++a) mx = fmaxf(mx, R.ms[a]);
        float e[ACT], s = 0.f;
        #pragma unroll
        for (int a = 0; a < ACT; ++a) { e[a] = expf(R.ms[a] - mx); s += e[a]; }
        float inv = 1.f / s;
        #pragma unroll
        for (int a = 0; a < ACT; ++a) out[b * ACT + a] = e[a] * inv;
        out[BATCHN * ACT + b] = R.ms[ACT];
    }
}

extern "C" void kernel_launch(void* const* d_in, const int* in_sizes, int n_in,
                              void* d_out, int out_size)
{
    const float* x        = (const float*)d_in[0];
    const float* w_in     = (const float*)d_in[1];
    const float* w_rec    = (const float*)d_in[2];
    const float* w_actor  = (const float*)d_in[3];
    const float* w_critic = (const float*)d_in[4];
    float* out = (float*)d_out;

    dim3 tgrid(16, 4), tblk(32, 8);
    transpose_win<<<tgrid, tblk>>>(w_in);

    cudaFuncSetAttribute(snn_kernel, cudaFuncAttributeMaxDynamicSharedMemorySize, (int)sizeof(Shm));
    int grid = (BATCHN + ROWS - 1) / ROWS;
    snn_kernel<<<grid, ROWS * HID, sizeof(Shm)>>>(x, w_in, w_rec, w_actor, w_critic, out);
}